// round 5
// baseline (speedup 1.0000x reference)
#include <cuda_runtime.h>
#include <cuda_bf16.h>
#include <cstdint>

#define Bb   16
#define LAT  8
#define NPTS 500000
#define XS   256
#define HALF 128
#define IMG_ELEMS (Bb * XS * XS)   // 1,048,576
#define NXH  129                   // Hermitian half-spectrum width

// ---------------- device scratch (static, no runtime allocation) ------------
__device__ float  g_img[IMG_ELEMS];          // 4 MB (scatter accumulator)
__device__ float  g_tmp[IMG_ELEMS];          // 4 MB (blurred image)
__device__ float2 g_Fc[Bb * NXH * XS];       // 4.2 MB column-major half spectrum
__device__ float2 g_G [Bb * XS * NXH];       // 4.2 MB row-major after col pipeline
__device__ float  g_R[Bb * 6];
__device__ float  g_sh[Bb * 2];
__device__ float  g_h[Bb * LAT];
__device__ float2 g_tw[128];                 // exp(-2*pi*i*k/256), k=0..127

#define REV8(i) ((int)(__brev((unsigned)(i)) >> 24))

// ---------------- prep: rotations, shifts, MLP h, twiddles ------------------
// (bit-identical to round-2 passing version)
__global__ void prep_kernel(const float* __restrict__ rows,
                            const float* __restrict__ shifts,
                            const float* __restrict__ latent,
                            const float* __restrict__ W0, const float* __restrict__ b0,
                            const float* __restrict__ W1, const float* __restrict__ b1,
                            const float* __restrict__ W2, const float* __restrict__ b2,
                            const float* __restrict__ W3, const float* __restrict__ b3)
{
    int t = threadIdx.x;
    if (t < 128) {
        float ang = -6.283185307179586f * (float)t / 256.0f;
        float s, c;
        sincosf(ang, &s, &c);
        g_tw[t] = make_float2(c, s);
    }
    if (t < Bb) {
        int b = t;
        float rot = rows[b*3+0], tilt = rows[b*3+1], psi = rows[b*3+2];
        float ca = cosf(rot),  sa = sinf(rot);
        float cb = cosf(tilt), sb = sinf(tilt);
        float cg = cosf(psi),  sg = sinf(psi);
        float cgcb = __fmul_rn(cg, cb);
        g_R[b*6+0] = __fsub_rn(__fmul_rn(cgcb, ca), __fmul_rn(sg, sa));
        g_R[b*6+1] = __fadd_rn(__fmul_rn(cgcb, sa), __fmul_rn(sg, ca));
        g_R[b*6+2] = __fmul_rn(-cg, sb);
        float msgcb = __fmul_rn(-sg, cb);
        g_R[b*6+3] = __fsub_rn(__fmul_rn(msgcb, ca), __fmul_rn(cg, sa));
        g_R[b*6+4] = __fadd_rn(__fmul_rn(msgcb, sa), __fmul_rn(cg, ca));
        g_R[b*6+5] = __fmul_rn(sg, sb);
        g_sh[b*2+0] = shifts[b*2+0];
        g_sh[b*2+1] = shifts[b*2+1];

        float h[LAT], l[LAT], tv[LAT];
        for (int i = 0; i < LAT; i++) l[i] = latent[b*LAT+i];
        for (int j = 0; j < LAT; j++) {
            float acc = 0.0f;
            for (int i = 0; i < LAT; i++) acc = __fmaf_rn(l[i], W0[i*LAT+j], acc);
            acc = __fadd_rn(acc, b0[j]);
            h[j] = sinf(30.0f * acc);
        }
        const float* Ws[3] = {W1, W2, W3};
        const float* bs[3] = {b1, b2, b3};
        for (int L = 0; L < 3; L++) {
            for (int j = 0; j < LAT; j++) {
                float acc = 0.0f;
                for (int i = 0; i < LAT; i++) acc = __fmaf_rn(h[i], Ws[L][i*LAT+j], acc);
                acc = __fadd_rn(acc, bs[L][j]);
                tv[j] = sinf(acc);
            }
            for (int j = 0; j < LAT; j++) h[j] = __fadd_rn(h[j], tv[j]);
        }
        for (int j = 0; j < LAT; j++) g_h[b*LAT+j] = h[j];
    }
}

// ---------------- zero image (vectorized) ------------------------------------
__global__ void zero_kernel()
{
    int i = blockIdx.x * blockDim.x + threadIdx.x;   // IMG_ELEMS/4 threads
    reinterpret_cast<float4*>(g_img)[i] = make_float4(0.f, 0.f, 0.f, 0.f);
}

// ---------------- scatter (bit-identical to round-2 passing version) --------
__global__ void scatter_kernel(const float* __restrict__ coords,
                               const float* __restrict__ values,
                               const float* __restrict__ Wd,
                               const float* __restrict__ bd)
{
    __shared__ float sR[Bb*6], sSh[Bb*2], sH[Bb*LAT];
    int t = threadIdx.x;
    if (t < Bb*6)   sR[t]  = g_R[t];
    if (t < Bb*2)   sSh[t] = g_sh[t];
    if (t < Bb*LAT) sH[t]  = g_h[t];
    __syncthreads();

    int n = blockIdx.x * blockDim.x + t;
    if (n >= NPTS) return;

    float c0 = coords[3*n+0];
    float c1 = coords[3*n+1];
    float c2 = coords[3*n+2];
    float val = values[n];
    float bdn = bd[n];

    float wd[LAT];
#pragma unroll
    for (int l = 0; l < LAT; l++) wd[l] = Wd[l*NPTS + n];

#pragma unroll
    for (int b = 0; b < Bb; b++) {
        float x = __fmul_rn(sR[b*6+0], c0);
        x = __fmaf_rn(sR[b*6+1], c1, x);
        x = __fmaf_rn(sR[b*6+2], c2, x);
        float y = __fmul_rn(sR[b*6+3], c0);
        y = __fmaf_rn(sR[b*6+4], c1, y);
        y = __fmaf_rn(sR[b*6+5], c2, y);
        x = __fadd_rn(__fadd_rn(x, sSh[b*2+0]), 128.0f);
        y = __fadd_rn(__fadd_rn(y, sSh[b*2+1]), 128.0f);
        float pxf = fminf(fmaxf(rintf(x), 0.0f), 255.0f);
        float pyf = fminf(fmaxf(rintf(y), 0.0f), 255.0f);
        int px = (int)pxf;
        int py = (int)pyf;

        float d = 0.0f;
#pragma unroll
        for (int l = 0; l < LAT; l++) d = __fmaf_rn(sH[b*LAT+l], wd[l], d);
        float contrib = __fadd_rn(val, __fadd_rn(d, bdn));

        int idx = (b << 16) | (py << 8) | px;
        atomicAdd(&g_img[idx], contrib);
    }
}

// ---------------- fused separable gaussian blur (single pass, tiled) --------
#define GW0 0.39905027f
#define GW1 0.24203622f
#define GW2 0.05400558f
#define GW3 0.00443305f

__global__ void blur_xy_kernel()
{
    __shared__ float raw[38 * 40];    // (32+6) x (32+6), row stride 40
    __shared__ float ytmp[32 * 40];   // 32 rows x 38 cols, row stride 40
    const float w[7] = {GW3, GW2, GW1, GW0, GW1, GW2, GW3};

    int tid = threadIdx.x;            // 256 threads
    int bid = blockIdx.x;             // 1024 = 16b * 8ty * 8tx
    int b  = bid >> 6;
    int ty = (bid >> 3) & 7;
    int tx = bid & 7;
    int gx0 = tx * 32 - 3;
    int gy0 = ty * 32 - 3;
    int bbase = b << 16;

    for (int i = tid; i < 38 * 38; i += 256) {
        int r = i / 38, c = i - r * 38;
        int gy = gy0 + r, gx = gx0 + c;
        float v = 0.0f;
        if (gy >= 0 && gy < XS && gx >= 0 && gx < XS)
            v = g_img[bbase | (gy << 8) | gx];
        raw[r * 40 + c] = v;
    }
    __syncthreads();

    for (int i = tid; i < 32 * 38; i += 256) {
        int r = i / 38, c = i - r * 38;
        float acc = 0.0f;
#pragma unroll
        for (int d = 0; d < 7; d++)
            acc += w[d] * raw[(r + d) * 40 + c];
        ytmp[r * 40 + c] = acc;
    }
    __syncthreads();

    int cx = tid & 31;
    int r0 = tid >> 5;
    for (int r = r0; r < 32; r += 8) {
        float acc = 0.0f;
#pragma unroll
        for (int d = 0; d < 7; d++)
            acc += w[d] * ytmp[r * 40 + cx + d];
        g_tmp[bbase | ((ty * 32 + r) << 8) | (tx * 32 + cx)] = acc;
    }
}

// ---------------- 256-pt radix-2 DIT FFT (bit-reversed input in smem) -------
__device__ __forceinline__ void fft256(float2* s, const float2* tw, int tid, bool inv)
{
#pragma unroll
    for (int len = 2; len <= 256; len <<= 1) {
        __syncthreads();
        int half = len >> 1;
        int k    = tid & (half - 1);
        int base = (tid & ~(half - 1)) << 1;
        float2 w = tw[k * (256 / len)];
        float wy = inv ? -w.y : w.y;
        float2 u = s[base + k];
        float2 v = s[base + k + half];
        float2 vw = make_float2(v.x*w.x - v.y*wy, v.x*wy + v.y*w.x);
        s[base + k]        = make_float2(u.x + vw.x, u.y + vw.y);
        s[base + k + half] = make_float2(u.x - vw.x, u.y - vw.y);
    }
    __syncthreads();
}

// ---- forward row FFT, two real rows packed as one complex FFT --------------
// Stores only x=0..128, COLUMN-major: g_Fc[((b*129+x)<<8) + y]
__global__ void fwd_rows_pair()
{
    __shared__ float2 s[256];
    __shared__ float2 stw[128];
    __shared__ float  r0s[256], r1s[256];
    int tid = threadIdx.x;                    // 0..127
    int bid = blockIdx.x;                     // b*128 + j
    int b = bid >> 7, j = bid & 127;
    int y0 = 2 * j, y1 = 2 * j + 1;
    int off0 = (b << 16) | (y0 << 8);
    int off1 = off0 + 256;

    stw[tid] = g_tw[tid];
    r0s[tid]       = g_tmp[off0 + tid];
    r0s[tid + 128] = g_tmp[off0 + tid + 128];
    r1s[tid]       = g_tmp[off1 + tid];
    r1s[tid + 128] = g_tmp[off1 + tid + 128];
    __syncthreads();

    int rv0 = REV8(tid);
    int rv1 = REV8(tid + 128);
    s[tid]       = make_float2(r0s[rv0], r1s[rv0]);
    s[tid + 128] = make_float2(r0s[rv1], r1s[rv1]);
    fft256(s, stw, tid, false);

    // unpack: F0[x] = (Z[x]+conj(Z[-x]))/2, F1[x] = (Z[x]-conj(Z[-x]))/(2i)
    int x = tid;                              // 0..127
    float2 Z  = s[x];
    float2 Zm = s[(256 - x) & 255];
    float2 F0 = make_float2(0.5f * (Z.x + Zm.x), 0.5f * (Z.y - Zm.y));
    float2 F1 = make_float2(0.5f * (Z.y + Zm.y), 0.5f * (Zm.x - Z.x));
    int cb = ((b * NXH + x) << 8);
    g_Fc[cb + y0] = F0;
    g_Fc[cb + y1] = F1;
    if (tid == 0) {                           // x = 128 (Nyquist, real)
        float2 Zn = s[128];
        int cb2 = ((b * NXH + 128) << 8);
        g_Fc[cb2 + y0] = make_float2(Zn.x, 0.0f);
        g_Fc[cb2 + y1] = make_float2(Zn.y, 0.0f);
    }
}

// ---- fused column pipeline: fwd FFT(y) -> *ctf -> inv FFT(y), x=0..128 -----
// Reads contiguous columns from g_Fc, writes row-major g_G[((b<<8)+y)*129 + x]
__global__ void fft_cols_ctf_k(const float* __restrict__ ctf)
{
    __shared__ float2 s[256];
    __shared__ float2 s2[256];
    __shared__ float2 stw[128];
    int tid = threadIdx.x;
    int bid = blockIdx.x;                     // b*129 + x
    int b = bid / NXH, x = bid - b * NXH;
    int base = (b * NXH + x) << 8;

    stw[tid] = g_tw[tid];
    s[tid]       = g_Fc[base + REV8(tid)];
    s[tid + 128] = g_Fc[base + REV8(tid + 128)];
    fft256(s, stw, tid, false);

#pragma unroll
    for (int p = 0; p < 2; p++) {
        int jj = tid + p * 128;
        int y  = REV8(jj);
        float c = ctf[(b * 256 + y) * NXH + x];
        float2 v = s[y];
        s2[jj] = make_float2(v.x * c, v.y * c);
    }
    fft256(s2, stw, tid, true);

    g_G[((b << 8) + tid)       * NXH + x] = s2[tid];
    g_G[((b << 8) + tid + 128) * NXH + x] = s2[tid + 128];
}

// ---- inverse row FFT, two Hermitian rows packed as one complex iFFT --------
// c2r semantics: the imaginary parts of bins x=0 and x=128 are IGNORED by
// numpy/cuFFT irfft. Zero them before packing; otherwise ifft(G_ext) is not
// real and the two packed rows cross-contaminate (the round-3 bug).
__global__ void inv_rows_pair(float* __restrict__ out)
{
    __shared__ float2 s[256];
    __shared__ float2 stw[128];
    __shared__ float2 gr0[NXH], gr1[NXH];
    int tid = threadIdx.x;
    int bid = blockIdx.x;                     // b*128 + j
    int b = bid >> 7, j = bid & 127;
    int y0 = 2 * j, y1 = 2 * j + 1;
    const float2* G0 = g_G + ((b << 8) + y0) * NXH;
    const float2* G1 = g_G + ((b << 8) + y1) * NXH;

    stw[tid] = g_tw[tid];
    gr0[tid] = G0[tid];
    gr1[tid] = G1[tid];
    if (tid == 0) {
        gr0[0]   = make_float2(G0[0].x,   0.0f);   // DC: drop imag (c2r)
        gr1[0]   = make_float2(G1[0].x,   0.0f);
        gr0[128] = make_float2(G0[128].x, 0.0f);   // Nyquist: drop imag (c2r)
        gr1[128] = make_float2(G1[128].x, 0.0f);
    }
    __syncthreads();

    // Z[n] = G0_ext[n] + i*G1_ext[n], placed bit-reversed
#pragma unroll
    for (int p = 0; p < 2; p++) {
        int idx = tid + p * 128;
        int n = REV8(idx);
        float2 z;
        if (n <= 128) {
            float2 a = gr0[n], c = gr1[n];
            z = make_float2(a.x - c.y, a.y + c.x);
        } else {
            int m = 256 - n;
            float2 a = gr0[m], c = gr1[m];
            z = make_float2(a.x + c.y, c.x - a.y);
        }
        s[idx] = z;
    }
    fft256(s, stw, tid, true);

    const float norm = 1.0f / 65536.0f;
    int off0 = (b << 16) | (y0 << 8);
    int off1 = off0 + 256;
    out[off0 + tid]       = s[tid].x * norm;
    out[off0 + tid + 128] = s[tid + 128].x * norm;
    out[off1 + tid]       = s[tid].y * norm;
    out[off1 + tid + 128] = s[tid + 128].y * norm;
}

// ---------------- launch -----------------------------------------------------
extern "C" void kernel_launch(void* const* d_in, const int* in_sizes, int n_in,
                              void* d_out, int out_size)
{
    const float* rows   = (const float*)d_in[0];
    const float* shifts = (const float*)d_in[1];
    const float* latent = (const float*)d_in[2];
    const float* coords = (const float*)d_in[3];
    const float* values = (const float*)d_in[4];
    const float* W0     = (const float*)d_in[5];
    const float* b0     = (const float*)d_in[6];
    const float* W1     = (const float*)d_in[7];
    const float* b1     = (const float*)d_in[8];
    const float* W2     = (const float*)d_in[9];
    const float* b2     = (const float*)d_in[10];
    const float* W3     = (const float*)d_in[11];
    const float* b3     = (const float*)d_in[12];
    const float* Wd     = (const float*)d_in[13];
    const float* bd     = (const float*)d_in[14];
    const float* ctf    = (const float*)d_in[15];
    float* out = (float*)d_out;

    prep_kernel<<<1, 128>>>(rows, shifts, latent, W0, b0, W1, b1, W2, b2, W3, b3);
    zero_kernel<<<IMG_ELEMS / 4 / 256, 256>>>();
    scatter_kernel<<<(NPTS + 255) / 256, 256>>>(coords, values, Wd, bd);
    blur_xy_kernel<<<1024, 256>>>();
    fwd_rows_pair<<<Bb * 128, 128>>>();
    fft_cols_ctf_k<<<Bb * NXH, 128>>>(ctf);
    inv_rows_pair<<<Bb * 128, 128>>>(out);
}

// round 6
// speedup vs baseline: 1.5773x; 1.5773x over previous
#include <cuda_runtime.h>
#include <cuda_bf16.h>
#include <cstdint>

#define Bb   16
#define LAT  8
#define NPTS 500000
#define XS   256
#define IMG_ELEMS (Bb * XS * XS)   // 1,048,576
#define NXH  129                   // Hermitian half-spectrum width
#define SSTR 132                   // g_S row stride (float2), 32B-aligned rows

// ---------------- device scratch (static, no runtime allocation) ------------
__device__ float  g_img[IMG_ELEMS];            // 4 MB (scatter accumulator)
__device__ float  g_tmp[IMG_ELEMS];            // 4 MB (blurred image)
__device__ float2 g_S[Bb * XS * SSTR];         // 4.3 MB half spectrum, row-major [b][y][x]
__device__ float  g_R[Bb * 6];
__device__ float  g_sh[Bb * 2];
__device__ float  g_h[Bb * LAT];
__device__ float2 g_tw[128];                   // exp(-2*pi*i*k/256)

#define REV8(i) ((int)(__brev((unsigned)(i)) >> 24))

// ---------------- prep (bit-identical to passing version) -------------------
__global__ void prep_kernel(const float* __restrict__ rows,
                            const float* __restrict__ shifts,
                            const float* __restrict__ latent,
                            const float* __restrict__ W0, const float* __restrict__ b0,
                            const float* __restrict__ W1, const float* __restrict__ b1,
                            const float* __restrict__ W2, const float* __restrict__ b2,
                            const float* __restrict__ W3, const float* __restrict__ b3)
{
    int t = threadIdx.x;
    if (t < 128) {
        float ang = -6.283185307179586f * (float)t / 256.0f;
        float s, c;
        sincosf(ang, &s, &c);
        g_tw[t] = make_float2(c, s);
    }
    if (t < Bb) {
        int b = t;
        float rot = rows[b*3+0], tilt = rows[b*3+1], psi = rows[b*3+2];
        float ca = cosf(rot),  sa = sinf(rot);
        float cb = cosf(tilt), sb = sinf(tilt);
        float cg = cosf(psi),  sg = sinf(psi);
        float cgcb = __fmul_rn(cg, cb);
        g_R[b*6+0] = __fsub_rn(__fmul_rn(cgcb, ca), __fmul_rn(sg, sa));
        g_R[b*6+1] = __fadd_rn(__fmul_rn(cgcb, sa), __fmul_rn(sg, ca));
        g_R[b*6+2] = __fmul_rn(-cg, sb);
        float msgcb = __fmul_rn(-sg, cb);
        g_R[b*6+3] = __fsub_rn(__fmul_rn(msgcb, ca), __fmul_rn(cg, sa));
        g_R[b*6+4] = __fadd_rn(__fmul_rn(msgcb, sa), __fmul_rn(cg, ca));
        g_R[b*6+5] = __fmul_rn(sg, sb);
        g_sh[b*2+0] = shifts[b*2+0];
        g_sh[b*2+1] = shifts[b*2+1];

        float h[LAT], l[LAT], tv[LAT];
        for (int i = 0; i < LAT; i++) l[i] = latent[b*LAT+i];
        for (int j = 0; j < LAT; j++) {
            float acc = 0.0f;
            for (int i = 0; i < LAT; i++) acc = __fmaf_rn(l[i], W0[i*LAT+j], acc);
            acc = __fadd_rn(acc, b0[j]);
            h[j] = sinf(30.0f * acc);
        }
        const float* Ws[3] = {W1, W2, W3};
        const float* bs[3] = {b1, b2, b3};
        for (int L = 0; L < 3; L++) {
            for (int j = 0; j < LAT; j++) {
                float acc = 0.0f;
                for (int i = 0; i < LAT; i++) acc = __fmaf_rn(h[i], Ws[L][i*LAT+j], acc);
                acc = __fadd_rn(acc, bs[L][j]);
                tv[j] = sinf(acc);
            }
            for (int j = 0; j < LAT; j++) h[j] = __fadd_rn(h[j], tv[j]);
        }
        for (int j = 0; j < LAT; j++) g_h[b*LAT+j] = h[j];
    }
}

// ---------------- zero image (vectorized) ------------------------------------
__global__ void zero_kernel()
{
    int i = blockIdx.x * blockDim.x + threadIdx.x;   // IMG_ELEMS/4 threads
    reinterpret_cast<float4*>(g_img)[i] = make_float4(0.f, 0.f, 0.f, 0.f);
}

// ---------------- scatter (bit-identical to passing version) ----------------
__global__ void scatter_kernel(const float* __restrict__ coords,
                               const float* __restrict__ values,
                               const float* __restrict__ Wd,
                               const float* __restrict__ bd)
{
    __shared__ float sR[Bb*6], sSh[Bb*2], sH[Bb*LAT];
    int t = threadIdx.x;
    if (t < Bb*6)   sR[t]  = g_R[t];
    if (t < Bb*2)   sSh[t] = g_sh[t];
    if (t < Bb*LAT) sH[t]  = g_h[t];
    __syncthreads();

    int n = blockIdx.x * blockDim.x + t;
    if (n >= NPTS) return;

    float c0 = coords[3*n+0];
    float c1 = coords[3*n+1];
    float c2 = coords[3*n+2];
    float val = values[n];
    float bdn = bd[n];

    float wd[LAT];
#pragma unroll
    for (int l = 0; l < LAT; l++) wd[l] = Wd[l*NPTS + n];

#pragma unroll
    for (int b = 0; b < Bb; b++) {
        float x = __fmul_rn(sR[b*6+0], c0);
        x = __fmaf_rn(sR[b*6+1], c1, x);
        x = __fmaf_rn(sR[b*6+2], c2, x);
        float y = __fmul_rn(sR[b*6+3], c0);
        y = __fmaf_rn(sR[b*6+4], c1, y);
        y = __fmaf_rn(sR[b*6+5], c2, y);
        x = __fadd_rn(__fadd_rn(x, sSh[b*2+0]), 128.0f);
        y = __fadd_rn(__fadd_rn(y, sSh[b*2+1]), 128.0f);
        float pxf = fminf(fmaxf(rintf(x), 0.0f), 255.0f);
        float pyf = fminf(fmaxf(rintf(y), 0.0f), 255.0f);
        int px = (int)pxf;
        int py = (int)pyf;

        float d = 0.0f;
#pragma unroll
        for (int l = 0; l < LAT; l++) d = __fmaf_rn(sH[b*LAT+l], wd[l], d);
        float contrib = __fadd_rn(val, __fadd_rn(d, bdn));

        int idx = (b << 16) | (py << 8) | px;
        atomicAdd(&g_img[idx], contrib);
    }
}

// ---------------- blur: full-width strips, division-free --------------------
#define GW0 0.39905027f
#define GW1 0.24203622f
#define GW2 0.05400558f
#define GW3 0.00443305f

__global__ void blur_strip_kernel()
{
    __shared__ float raw[22 * 256];      // rows y0-3 .. y0+18
    __shared__ float ytmp[16 * 264];     // data at cols 3..258, zero borders
    const float w[7] = {GW3, GW2, GW1, GW0, GW1, GW2, GW3};

    int tid = threadIdx.x;               // 256 threads
    int bid = blockIdx.x;                // 256 = 16 batches x 16 strips
    int b  = bid >> 4;
    int y0 = (bid & 15) << 4;
    int bbase = b << 16;

    // load 22 halo rows, coalesced, zero outside image
#pragma unroll
    for (int k = 0; k < 22; k++) {
        int gy = y0 + k - 3;
        float v = (gy >= 0 && gy < XS) ? g_img[bbase | (gy << 8) | tid] : 0.0f;
        raw[(k << 8) | tid] = v;
    }
    // zero ytmp column borders (cols 0-2 and 259-261 of each row)
    if (tid < 96) {
        int r = tid / 6, p = tid - r * 6;
        int col = (p < 3) ? p : (256 + p);   // 0,1,2, 259,260,261
        ytmp[r * 264 + col] = 0.0f;
    }
    __syncthreads();

    // y-pass: 16 rows x 256 cols
#pragma unroll
    for (int r = 0; r < 16; r++) {
        float acc = 0.0f;
#pragma unroll
        for (int d = 0; d < 7; d++)
            acc += w[d] * raw[((r + d) << 8) | tid];
        ytmp[r * 264 + 3 + tid] = acc;
    }
    __syncthreads();

    // x-pass: 16 rows x 256 cols
#pragma unroll
    for (int r = 0; r < 16; r++) {
        float acc = 0.0f;
#pragma unroll
        for (int d = 0; d < 7; d++)
            acc += w[d] * ytmp[r * 264 + tid + d];
        g_tmp[bbase | ((y0 + r) << 8) | tid] = acc;
    }
}

// ---------------- forward row FFT: 2 real rows packed, DIF (no bitrev) ------
// Stores half spectrum row-major: g_S[(b*256+y)*SSTR + x], x=0..128
__global__ void fwd_rows_pair()
{
    __shared__ float2 s[256];
    __shared__ float2 stw[128];
    int tid = threadIdx.x;                    // 0..127
    int bid = blockIdx.x;                     // b*128 + j
    int b = bid >> 7, j = bid & 127;
    int y0 = 2 * j, y1 = y0 + 1;
    int off0 = (b << 16) | (y0 << 8);
    int off1 = off0 + 256;

    stw[tid] = g_tw[tid];
    s[tid]       = make_float2(g_tmp[off0 + tid],       g_tmp[off1 + tid]);
    s[tid + 128] = make_float2(g_tmp[off0 + tid + 128], g_tmp[off1 + tid + 128]);

    // DIF forward: natural in -> bit-reversed out
#pragma unroll
    for (int st = 0; st < 8; st++) {
        __syncthreads();
        int half = 128 >> st;
        int k    = tid & (half - 1);
        int i0   = ((tid & ~(half - 1)) << 1) + k;
        int i1   = i0 + half;
        float2 w = stw[k << st];
        float2 u = s[i0], v = s[i1];
        s[i0] = make_float2(u.x + v.x, u.y + v.y);
        float dx = u.x - v.x, dy = u.y - v.y;
        s[i1] = make_float2(dx*w.x - dy*w.y, dx*w.y + dy*w.x);
    }
    __syncthreads();

    // unpack two real spectra from bit-reversed Z; store coalesced
    int x = tid;
    float2 Z  = s[REV8(x)];
    float2 Zm = s[REV8((256 - x) & 255)];
    float2 F0 = make_float2(0.5f * (Z.x + Zm.x), 0.5f * (Z.y - Zm.y));
    float2 F1 = make_float2(0.5f * (Z.y + Zm.y), 0.5f * (Zm.x - Z.x));
    int r0 = (b * 256 + y0) * SSTR;
    int r1 = (b * 256 + y1) * SSTR;
    g_S[r0 + x] = F0;
    g_S[r1 + x] = F1;
    if (tid == 0) {                           // x = 128 (Nyquist of row FFT)
        float2 Zn = s[1];                     // REV8(128) = 1
        g_S[r0 + 128] = make_float2(Zn.x, 0.0f);
        g_S[r1 + 128] = make_float2(Zn.y, 0.0f);
    }
}

// ---------------- column pipeline: 16 x-columns per block, in-place ---------
// fwd DIF over y -> *ctf at bit-reversed y -> inv DIT over y. All global
// accesses 128B-contiguous per 16-lane group.
__global__ void fft_cols_ctf_k(const float* __restrict__ ctf)
{
    __shared__ float2 s[256 * 17];            // [y][xi], pad 17
    __shared__ float2 stw[128];
    int t  = threadIdx.x;                     // 256
    int xi = t & 15, tb = t >> 4;             // column-in-tile, row group
    int bid = blockIdx.x;                     // b*9 + tile
    int b = bid / 9, tile = bid - b * 9;
    int x = (tile << 4) + xi;
    bool xok = (x <= 128);
    if (t < 128) stw[t] = g_tw[t];

    // load 256 y values for 16 columns (coalesced 128B per 16-lane group)
#pragma unroll
    for (int k = 0; k < 16; k++) {
        int y = (k << 4) + tb;
        float2 v = xok ? g_S[(b * 256 + y) * SSTR + x] : make_float2(0.f, 0.f);
        s[y * 17 + xi] = v;
    }

    // DIF forward over y
#pragma unroll
    for (int st = 0; st < 8; st++) {
        __syncthreads();
        int half = 128 >> st;
#pragma unroll
        for (int k = 0; k < 8; k++) {
            int bf = (k << 4) + tb;
            int kk = bf & (half - 1);
            int i0 = ((bf & ~(half - 1)) << 1) + kk;
            int i1 = i0 + half;
            float2 w = stw[kk << st];
            float2 u = s[i0 * 17 + xi], v = s[i1 * 17 + xi];
            s[i0 * 17 + xi] = make_float2(u.x + v.x, u.y + v.y);
            float dx = u.x - v.x, dy = u.y - v.y;
            s[i1 * 17 + xi] = make_float2(dx*w.x - dy*w.y, dx*w.y + dy*w.x);
        }
    }
    __syncthreads();

    // ctf multiply at bit-reversed positions
#pragma unroll
    for (int k = 0; k < 16; k++) {
        int j = (k << 4) + tb;
        int y = REV8(j);
        float c = xok ? ctf[(b * 256 + y) * NXH + x] : 0.0f;
        float2 v = s[j * 17 + xi];
        s[j * 17 + xi] = make_float2(v.x * c, v.y * c);
    }

    // DIT inverse over y (bit-reversed in -> natural out)
#pragma unroll
    for (int st = 0; st < 8; st++) {
        __syncthreads();
        int half = 1 << st;
#pragma unroll
        for (int k = 0; k < 8; k++) {
            int bf = (k << 4) + tb;
            int kk = bf & (half - 1);
            int i0 = ((bf & ~(half - 1)) << 1) + kk;
            int i1 = i0 + half;
            float2 w = stw[kk << (7 - st)];
            float2 u = s[i0 * 17 + xi], v = s[i1 * 17 + xi];
            float vwx = v.x * w.x + v.y * w.y;     // v * conj(w)
            float vwy = v.y * w.x - v.x * w.y;
            s[i0 * 17 + xi] = make_float2(u.x + vwx, u.y + vwy);
            s[i1 * 17 + xi] = make_float2(u.x - vwx, u.y - vwy);
        }
    }
    __syncthreads();

    // store back in place (coalesced)
#pragma unroll
    for (int k = 0; k < 16; k++) {
        int y = (k << 4) + tb;
        if (xok) g_S[(b * 256 + y) * SSTR + x] = s[y * 17 + xi];
    }
}

// ---------------- inverse row FFT: 2 Hermitian rows packed, DIT -------------
// c2r semantics: imag of bins x=0 and x=128 is ignored (zeroed before pack).
__global__ void inv_rows_pair(float* __restrict__ out)
{
    __shared__ float2 s[256];
    __shared__ float2 stw[128];
    __shared__ float2 gr0[NXH], gr1[NXH];
    int tid = threadIdx.x;                    // 0..127
    int bid = blockIdx.x;                     // b*128 + j
    int b = bid >> 7, j = bid & 127;
    int y0 = 2 * j, y1 = y0 + 1;
    int r0 = (b * 256 + y0) * SSTR;
    int r1 = (b * 256 + y1) * SSTR;

    stw[tid] = g_tw[tid];
    gr0[tid] = g_S[r0 + tid];
    gr1[tid] = g_S[r1 + tid];
    if (tid == 0) {
        gr0[0]   = make_float2(g_S[r0].x,       0.0f);
        gr1[0]   = make_float2(g_S[r1].x,       0.0f);
        gr0[128] = make_float2(g_S[r0 + 128].x, 0.0f);
        gr1[128] = make_float2(g_S[r1 + 128].x, 0.0f);
    }
    __syncthreads();

    // Z[n] = G0_ext[n] + i*G1_ext[n], placed at bit-reversed index
#pragma unroll
    for (int p = 0; p < 2; p++) {
        int idx = tid + p * 128;
        int n = REV8(idx);
        float2 z;
        if (n <= 128) {
            float2 a = gr0[n], c = gr1[n];
            z = make_float2(a.x - c.y, a.y + c.x);
        } else {
            int m = 256 - n;
            float2 a = gr0[m], c = gr1[m];
            z = make_float2(a.x + c.y, c.x - a.y);
        }
        s[idx] = z;
    }

    // DIT inverse (bit-reversed in -> natural out)
#pragma unroll
    for (int st = 0; st < 8; st++) {
        __syncthreads();
        int half = 1 << st;
        int k    = tid & (half - 1);
        int i0   = ((tid & ~(half - 1)) << 1) + k;
        int i1   = i0 + half;
        float2 w = stw[k << (7 - st)];
        float2 u = s[i0], v = s[i1];
        float vwx = v.x * w.x + v.y * w.y;
        float vwy = v.y * w.x - v.x * w.y;
        s[i0] = make_float2(u.x + vwx, u.y + vwy);
        s[i1] = make_float2(u.x - vwx, u.y - vwy);
    }
    __syncthreads();

    const float norm = 1.0f / 65536.0f;
    int off0 = (b << 16) | (y0 << 8);
    int off1 = off0 + 256;
    out[off0 + tid]       = s[tid].x * norm;
    out[off0 + tid + 128] = s[tid + 128].x * norm;
    out[off1 + tid]       = s[tid].y * norm;
    out[off1 + tid + 128] = s[tid + 128].y * norm;
}

// ---------------- launch -----------------------------------------------------
extern "C" void kernel_launch(void* const* d_in, const int* in_sizes, int n_in,
                              void* d_out, int out_size)
{
    const float* rows   = (const float*)d_in[0];
    const float* shifts = (const float*)d_in[1];
    const float* latent = (const float*)d_in[2];
    const float* coords = (const float*)d_in[3];
    const float* values = (const float*)d_in[4];
    const float* W0     = (const float*)d_in[5];
    const float* b0     = (const float*)d_in[6];
    const float* W1     = (const float*)d_in[7];
    const float* b1     = (const float*)d_in[8];
    const float* W2     = (const float*)d_in[9];
    const float* b2     = (const float*)d_in[10];
    const float* W3     = (const float*)d_in[11];
    const float* b3     = (const float*)d_in[12];
    const float* Wd     = (const float*)d_in[13];
    const float* bd     = (const float*)d_in[14];
    const float* ctf    = (const float*)d_in[15];
    float* out = (float*)d_out;

    prep_kernel<<<1, 128>>>(rows, shifts, latent, W0, b0, W1, b1, W2, b2, W3, b3);
    zero_kernel<<<IMG_ELEMS / 4 / 256, 256>>>();
    scatter_kernel<<<(NPTS + 255) / 256, 256>>>(coords, values, Wd, bd);
    blur_strip_kernel<<<Bb * 16, 256>>>();
    fwd_rows_pair<<<Bb * 128, 128>>>();
    fft_cols_ctf_k<<<Bb * 9, 256>>>(ctf);
    inv_rows_pair<<<Bb * 128, 128>>>(out);
}

// round 7
// speedup vs baseline: 1.7055x; 1.0813x over previous
#include <cuda_runtime.h>
#include <cuda_bf16.h>
#include <cstdint>

#define Bb   16
#define LAT  8
#define NPTS 500000
#define XS   256
#define IMG_ELEMS (Bb * XS * XS)   // 1,048,576
#define NXH  129                   // Hermitian half-spectrum width
#define SSTR 132                   // g_S row stride (float2)

// ---------------- device scratch (static, no runtime allocation) ------------
__device__ float  g_img[IMG_ELEMS];            // 4 MB (scatter accumulator)
__device__ float2 g_S[Bb * XS * SSTR];         // 4.3 MB half spectrum [b][y][x]
__device__ float  g_R[Bb * 6];
__device__ float  g_sh[Bb * 2];
__device__ float  g_h[Bb * LAT];
__device__ float2 g_tw[128];                   // exp(-2*pi*i*k/256)

#define REV8(i) ((int)(__brev((unsigned)(i)) >> 24))
__device__ __constant__ int BR4[16] = {0,8,4,12,2,10,6,14,1,9,5,13,3,11,7,15};

__device__ __forceinline__ float2 cmul(float2 a, float2 b)
{ return make_float2(a.x*b.x - a.y*b.y, a.x*b.y + a.y*b.x); }
__device__ __forceinline__ float2 cmulc(float2 a, float2 b)   // a * conj(b)
{ return make_float2(a.x*b.x + a.y*b.y, a.y*b.x - a.x*b.y); }

// ---------------- prep (bit-identical to passing version) -------------------
__global__ void prep_kernel(const float* __restrict__ rows,
                            const float* __restrict__ shifts,
                            const float* __restrict__ latent,
                            const float* __restrict__ W0, const float* __restrict__ b0,
                            const float* __restrict__ W1, const float* __restrict__ b1,
                            const float* __restrict__ W2, const float* __restrict__ b2,
                            const float* __restrict__ W3, const float* __restrict__ b3)
{
    int t = threadIdx.x;
    if (t < 128) {
        float ang = -6.283185307179586f * (float)t / 256.0f;
        float s, c;
        sincosf(ang, &s, &c);
        g_tw[t] = make_float2(c, s);
    }
    if (t < Bb) {
        int b = t;
        float rot = rows[b*3+0], tilt = rows[b*3+1], psi = rows[b*3+2];
        float ca = cosf(rot),  sa = sinf(rot);
        float cb = cosf(tilt), sb = sinf(tilt);
        float cg = cosf(psi),  sg = sinf(psi);
        float cgcb = __fmul_rn(cg, cb);
        g_R[b*6+0] = __fsub_rn(__fmul_rn(cgcb, ca), __fmul_rn(sg, sa));
        g_R[b*6+1] = __fadd_rn(__fmul_rn(cgcb, sa), __fmul_rn(sg, ca));
        g_R[b*6+2] = __fmul_rn(-cg, sb);
        float msgcb = __fmul_rn(-sg, cb);
        g_R[b*6+3] = __fsub_rn(__fmul_rn(msgcb, ca), __fmul_rn(cg, sa));
        g_R[b*6+4] = __fadd_rn(__fmul_rn(msgcb, sa), __fmul_rn(cg, ca));
        g_R[b*6+5] = __fmul_rn(sg, sb);
        g_sh[b*2+0] = shifts[b*2+0];
        g_sh[b*2+1] = shifts[b*2+1];

        float h[LAT], l[LAT], tv[LAT];
        for (int i = 0; i < LAT; i++) l[i] = latent[b*LAT+i];
        for (int j = 0; j < LAT; j++) {
            float acc = 0.0f;
            for (int i = 0; i < LAT; i++) acc = __fmaf_rn(l[i], W0[i*LAT+j], acc);
            acc = __fadd_rn(acc, b0[j]);
            h[j] = sinf(30.0f * acc);
        }
        const float* Ws[3] = {W1, W2, W3};
        const float* bs[3] = {b1, b2, b3};
        for (int L = 0; L < 3; L++) {
            for (int j = 0; j < LAT; j++) {
                float acc = 0.0f;
                for (int i = 0; i < LAT; i++) acc = __fmaf_rn(h[i], Ws[L][i*LAT+j], acc);
                acc = __fadd_rn(acc, bs[L][j]);
                tv[j] = sinf(acc);
            }
            for (int j = 0; j < LAT; j++) h[j] = __fadd_rn(h[j], tv[j]);
        }
        for (int j = 0; j < LAT; j++) g_h[b*LAT+j] = h[j];
    }
}

// ---------------- zero image (vectorized) ------------------------------------
__global__ void zero_kernel()
{
    int i = blockIdx.x * blockDim.x + threadIdx.x;
    reinterpret_cast<float4*>(g_img)[i] = make_float4(0.f, 0.f, 0.f, 0.f);
}

// ---------------- scatter (bit-identical to passing version) ----------------
__global__ void scatter_kernel(const float* __restrict__ coords,
                               const float* __restrict__ values,
                               const float* __restrict__ Wd,
                               const float* __restrict__ bd)
{
    __shared__ float sR[Bb*6], sSh[Bb*2], sH[Bb*LAT];
    int t = threadIdx.x;
    if (t < Bb*6)   sR[t]  = g_R[t];
    if (t < Bb*2)   sSh[t] = g_sh[t];
    if (t < Bb*LAT) sH[t]  = g_h[t];
    __syncthreads();

    int n = blockIdx.x * blockDim.x + t;
    if (n >= NPTS) return;

    float c0 = coords[3*n+0];
    float c1 = coords[3*n+1];
    float c2 = coords[3*n+2];
    float val = values[n];
    float bdn = bd[n];

    float wd[LAT];
#pragma unroll
    for (int l = 0; l < LAT; l++) wd[l] = Wd[l*NPTS + n];

#pragma unroll
    for (int b = 0; b < Bb; b++) {
        float x = __fmul_rn(sR[b*6+0], c0);
        x = __fmaf_rn(sR[b*6+1], c1, x);
        x = __fmaf_rn(sR[b*6+2], c2, x);
        float y = __fmul_rn(sR[b*6+3], c0);
        y = __fmaf_rn(sR[b*6+4], c1, y);
        y = __fmaf_rn(sR[b*6+5], c2, y);
        x = __fadd_rn(__fadd_rn(x, sSh[b*2+0]), 128.0f);
        y = __fadd_rn(__fadd_rn(y, sSh[b*2+1]), 128.0f);
        float pxf = fminf(fmaxf(rintf(x), 0.0f), 255.0f);
        float pyf = fminf(fmaxf(rintf(y), 0.0f), 255.0f);
        int px = (int)pxf;
        int py = (int)pyf;

        float d = 0.0f;
#pragma unroll
        for (int l = 0; l < LAT; l++) d = __fmaf_rn(sH[b*LAT+l], wd[l], d);
        float contrib = __fadd_rn(val, __fadd_rn(d, bdn));

        int idx = (b << 16) | (py << 8) | px;
        atomicAdd(&g_img[idx], contrib);
    }
}

// ---------------- fused blur + forward row FFT -------------------------------
// Blur MAC order identical to previous passing version (bit-identical), then
// packed 2-real-row DIF FFT, half-spectrum stored coalesced into g_S.
#define GW0 0.39905027f
#define GW1 0.24203622f
#define GW2 0.05400558f
#define GW3 0.00443305f

__global__ void fwd_rows_blur()
{
    __shared__ float  raw[8 * 256];      // img rows y0-3 .. y0+4
    __shared__ float  ybl[2 * 264];      // y-blurred rows, 3-zero col borders
    __shared__ float2 s[256];
    __shared__ float2 stw[128];
    const float w[7] = {GW3, GW2, GW1, GW0, GW1, GW2, GW3};

    int tid = threadIdx.x;               // 0..127
    int bid = blockIdx.x;                // b*128 + j
    int b = bid >> 7, j = bid & 127;
    int y0 = 2 * j;
    int bbase = b << 16;

    stw[tid] = g_tw[tid];
#pragma unroll
    for (int k = 0; k < 8; k++) {
        int gy = y0 + k - 3;
        bool ok = (gy >= 0 && gy < XS);
        raw[(k << 8) | tid]         = ok ? g_img[bbase | (gy << 8) | tid]         : 0.0f;
        raw[(k << 8) | (tid + 128)] = ok ? g_img[bbase | (gy << 8) | (tid + 128)] : 0.0f;
    }
    if (tid < 12) {
        int r = tid / 6, p = tid - r * 6;
        int col = (p < 3) ? p : (256 + p);   // 0,1,2, 259,260,261
        ybl[r * 264 + col] = 0.0f;
    }
    __syncthreads();

    // y-pass for the 2 target rows, both column halves
#pragma unroll
    for (int r = 0; r < 2; r++) {
#pragma unroll
        for (int p = 0; p < 2; p++) {
            int c = tid + (p << 7);
            float acc = 0.0f;
#pragma unroll
            for (int d = 0; d < 7; d++)
                acc += w[d] * raw[((r + d) << 8) | c];
            ybl[r * 264 + 3 + c] = acc;
        }
    }
    __syncthreads();

    // x-pass -> pack the two real rows into one complex sequence
#pragma unroll
    for (int p = 0; p < 2; p++) {
        int c = tid + (p << 7);
        float a0 = 0.0f, a1 = 0.0f;
#pragma unroll
        for (int d = 0; d < 7; d++) {
            a0 += w[d] * ybl[0 * 264 + c + d];
            a1 += w[d] * ybl[1 * 264 + c + d];
        }
        s[c] = make_float2(a0, a1);
    }

    // DIF forward 256: natural in -> bit-reversed out
#pragma unroll
    for (int st = 0; st < 8; st++) {
        __syncthreads();
        int half = 128 >> st;
        int k    = tid & (half - 1);
        int i0   = ((tid & ~(half - 1)) << 1) + k;
        int i1   = i0 + half;
        float2 tw = stw[k << st];
        float2 u = s[i0], v = s[i1];
        s[i0] = make_float2(u.x + v.x, u.y + v.y);
        float dx = u.x - v.x, dy = u.y - v.y;
        s[i1] = make_float2(dx*tw.x - dy*tw.y, dx*tw.y + dy*tw.x);
    }
    __syncthreads();

    // unpack two real spectra; store coalesced half spectrum
    int x = tid;
    float2 Z  = s[REV8(x)];
    float2 Zm = s[REV8((256 - x) & 255)];
    float2 F0 = make_float2(0.5f * (Z.x + Zm.x), 0.5f * (Z.y - Zm.y));
    float2 F1 = make_float2(0.5f * (Z.y + Zm.y), 0.5f * (Zm.x - Z.x));
    int r0 = (b * 256 + y0)     * SSTR;
    int r1 = (b * 256 + y0 + 1) * SSTR;
    g_S[r0 + x] = F0;
    g_S[r1 + x] = F1;
    if (tid == 0) {                            // x = 128 (Nyquist)
        float2 Zn = s[1];                      // REV8(128) = 1
        g_S[r0 + 128] = make_float2(Zn.x, 0.0f);
        g_S[r1 + 128] = make_float2(Zn.y, 0.0f);
    }
}

// ---------------- register-resident FFT16 helpers ----------------------------
// DIF: natural input -> bit-reversed output. conj_tw selects conjugate twiddles.
__device__ __forceinline__ void fft16_dif(float2* r, const float2* stw, bool conj_tw)
{
#pragma unroll
    for (int st = 0; st < 4; st++) {
        int half = 8 >> st;
#pragma unroll
        for (int base = 0; base < 16; base += 16 >> st) {
#pragma unroll
            for (int k = 0; k < 8; k++) {
                if (k < half) {
                    int i0 = base + k, i1 = i0 + half;
                    float2 u = r[i0], v = r[i1];
                    r[i0] = make_float2(u.x + v.x, u.y + v.y);
                    float2 d = make_float2(u.x - v.x, u.y - v.y);
                    float2 tw = stw[k << (4 + st)];      // W16^(k*2^st)
                    r[i1] = conj_tw ? cmulc(d, tw) : cmul(d, tw);
                }
            }
        }
    }
}

// DIT with conjugate twiddles: bit-reversed input -> natural output (inverse).
__device__ __forceinline__ void fft16_dit_conj(float2* r, const float2* stw)
{
#pragma unroll
    for (int st = 0; st < 4; st++) {
        int half = 1 << st;
#pragma unroll
        for (int base = 0; base < 16; base += 2 << st) {
#pragma unroll
            for (int k = 0; k < 8; k++) {
                if (k < half) {
                    int i0 = base + k, i1 = i0 + half;
                    float2 tw = stw[k << (7 - st)];      // W16^(k*2^(3-st))
                    float2 u = r[i0];
                    float2 t = cmulc(r[i1], tw);
                    r[i0] = make_float2(u.x + t.x, u.y + t.y);
                    r[i1] = make_float2(u.x - t.x, u.y - t.y);
                }
            }
        }
    }
}

// ---------------- column pipeline: four-step 16x16, 16 x-cols per block ------
// fwd FFT(y) -> *ctf -> inv FFT(y), 3 barriers total, butterflies in registers.
__global__ void fft_cols_ctf_k(const float* __restrict__ ctf)
{
    __shared__ float2 sm[256 * 17];
    __shared__ float2 stw[128];
    int t  = threadIdx.x;                 // 256
    int xi = t & 15, tb = t >> 4;         // x-in-tile, n2/k1 role (0..15)
    int bid = blockIdx.x;                 // b*9 + tile
    int b = bid / 9, tile = bid - b * 9;
    int x = (tile << 4) + xi;
    bool xok = (x <= 128);
    if (t < 128) stw[t] = g_tw[t];
    __syncthreads();

    // step 1: load x[16*n1 + tb] (stride-16 in y), FFT16 over n1
    float2 r[16];
#pragma unroll
    for (int n1 = 0; n1 < 16; n1++)
        r[n1] = xok ? g_S[(b * 256 + (n1 << 4) + tb) * SSTR + x]
                    : make_float2(0.f, 0.f);
    fft16_dif(r, stw, false);             // reg i holds A[k1 = BR4[i]]

    // step 2 twiddle W^(tb*k1) + transpose write
#pragma unroll
    for (int i = 0; i < 16; i++) {
        int k1 = BR4[i];
        int idx = (tb * k1) & 255;
        float2 tw = stw[idx & 127];
        if (idx & 128) tw = make_float2(-tw.x, -tw.y);
        sm[(k1 * 16 + tb) * 17 + xi] = cmul(r[i], tw);
    }
    __syncthreads();

    // step 3: FFT16 over n2 (thread role: k1 = tb)
    float2 c[16];
#pragma unroll
    for (int n2 = 0; n2 < 16; n2++)
        c[n2] = sm[(tb * 16 + n2) * 17 + xi];
    fft16_dif(c, stw, false);             // reg i holds X[y = tb + 16*BR4[i]]

    // ctf multiply at natural y
#pragma unroll
    for (int i = 0; i < 16; i++) {
        int y = tb + (BR4[i] << 4);
        float cc = xok ? ctf[(b * 256 + y) * NXH + x] : 0.0f;
        c[i].x *= cc; c[i].y *= cc;
    }

    // inverse step 1: IFFT16 over k2 (bitrev input -> natural n2)
    fft16_dit_conj(c, stw);
    // inverse step 2: * W^(-tb*n2)
#pragma unroll
    for (int n2 = 0; n2 < 16; n2++) {
        int idx = (tb * n2) & 255;
        float2 tw = stw[idx & 127];
        if (idx & 128) tw = make_float2(-tw.x, -tw.y);
        c[n2] = cmulc(c[n2], tw);
    }
    __syncthreads();                      // all step-3 reads done before overwrite
#pragma unroll
    for (int n2 = 0; n2 < 16; n2++)
        sm[(n2 * 16 + tb) * 17 + xi] = c[n2];
    __syncthreads();

    // inverse step 3: IFFT16 over k1 (thread role: n2 = tb)
    float2 e[16];
#pragma unroll
    for (int k1 = 0; k1 < 16; k1++)
        e[k1] = sm[(tb * 16 + k1) * 17 + xi];
    fft16_dif(e, stw, true);              // reg i holds x at n1 = BR4[i]

#pragma unroll
    for (int i = 0; i < 16; i++) {
        int y = (BR4[i] << 4) + tb;
        if (xok) g_S[(b * 256 + y) * SSTR + x] = e[i];
    }
}

// ---------------- inverse row FFT: 2 Hermitian rows packed, DIT -------------
__global__ void inv_rows_pair(float* __restrict__ out)
{
    __shared__ float2 s[256];
    __shared__ float2 stw[128];
    __shared__ float2 gr0[NXH], gr1[NXH];
    int tid = threadIdx.x;                // 0..127
    int bid = blockIdx.x;                 // b*128 + j
    int b = bid >> 7, j = bid & 127;
    int y0 = 2 * j, y1 = y0 + 1;
    int r0 = (b * 256 + y0) * SSTR;
    int r1 = (b * 256 + y1) * SSTR;

    stw[tid] = g_tw[tid];
    gr0[tid] = g_S[r0 + tid];
    gr1[tid] = g_S[r1 + tid];
    if (tid == 0) {
        gr0[0]   = make_float2(g_S[r0].x,       0.0f);
        gr1[0]   = make_float2(g_S[r1].x,       0.0f);
        gr0[128] = make_float2(g_S[r0 + 128].x, 0.0f);
        gr1[128] = make_float2(g_S[r1 + 128].x, 0.0f);
    }
    __syncthreads();

#pragma unroll
    for (int p = 0; p < 2; p++) {
        int idx = tid + p * 128;
        int n = REV8(idx);
        float2 z;
        if (n <= 128) {
            float2 a = gr0[n], c = gr1[n];
            z = make_float2(a.x - c.y, a.y + c.x);
        } else {
            int m = 256 - n;
            float2 a = gr0[m], c = gr1[m];
            z = make_float2(a.x + c.y, c.x - a.y);
        }
        s[idx] = z;
    }

#pragma unroll
    for (int st = 0; st < 8; st++) {
        __syncthreads();
        int half = 1 << st;
        int k    = tid & (half - 1);
        int i0   = ((tid & ~(half - 1)) << 1) + k;
        int i1   = i0 + half;
        float2 w = stw[k << (7 - st)];
        float2 u = s[i0], v = s[i1];
        float vwx = v.x * w.x + v.y * w.y;
        float vwy = v.y * w.x - v.x * w.y;
        s[i0] = make_float2(u.x + vwx, u.y + vwy);
        s[i1] = make_float2(u.x - vwx, u.y - vwy);
    }
    __syncthreads();

    const float norm = 1.0f / 65536.0f;
    int off0 = (b << 16) | (y0 << 8);
    int off1 = off0 + 256;
    out[off0 + tid]       = s[tid].x * norm;
    out[off0 + tid + 128] = s[tid + 128].x * norm;
    out[off1 + tid]       = s[tid].y * norm;
    out[off1 + tid + 128] = s[tid + 128].y * norm;
}

// ---------------- launch -----------------------------------------------------
extern "C" void kernel_launch(void* const* d_in, const int* in_sizes, int n_in,
                              void* d_out, int out_size)
{
    const float* rows   = (const float*)d_in[0];
    const float* shifts = (const float*)d_in[1];
    const float* latent = (const float*)d_in[2];
    const float* coords = (const float*)d_in[3];
    const float* values = (const float*)d_in[4];
    const float* W0     = (const float*)d_in[5];
    const float* b0     = (const float*)d_in[6];
    const float* W1     = (const float*)d_in[7];
    const float* b1     = (const float*)d_in[8];
    const float* W2     = (const float*)d_in[9];
    const float* b2     = (const float*)d_in[10];
    const float* W3     = (const float*)d_in[11];
    const float* b3     = (const float*)d_in[12];
    const float* Wd     = (const float*)d_in[13];
    const float* bd     = (const float*)d_in[14];
    const float* ctf    = (const float*)d_in[15];
    float* out = (float*)d_out;

    prep_kernel<<<1, 128>>>(rows, shifts, latent, W0, b0, W1, b1, W2, b2, W3, b3);
    zero_kernel<<<IMG_ELEMS / 4 / 256, 256>>>();
    scatter_kernel<<<(NPTS + 255) / 256, 256>>>(coords, values, Wd, bd);
    fwd_rows_blur<<<Bb * 128, 128>>>();
    fft_cols_ctf_k<<<Bb * 9, 256>>>(ctf);
    inv_rows_pair<<<Bb * 128, 128>>>(out);
}

// round 8
// speedup vs baseline: 1.7454x; 1.0234x over previous
#include <cuda_runtime.h>
#include <cuda_bf16.h>
#include <cstdint>

#define Bb   16
#define LAT  8
#define NPTS 500000
#define XS   256
#define IMG_ELEMS (Bb * XS * XS)   // 1,048,576
#define NXH  129                   // Hermitian half-spectrum width
#define SSTR 132                   // g_S row stride (float2)

// ---------------- device scratch (static, no runtime allocation) ------------
__device__ float  g_img[IMG_ELEMS];            // 4 MB (scatter accumulator)
__device__ float2 g_S[Bb * XS * SSTR];         // 4.3 MB half spectrum [b][y][x]
__device__ float  g_R[Bb * 6];
__device__ float  g_sh[Bb * 2];
__device__ float  g_h[Bb * LAT];
__device__ float2 g_tw[128];                   // exp(-2*pi*i*k/256)

#define REV8(i) ((int)(__brev((unsigned)(i)) >> 24))
__device__ __constant__ int BR4[16] = {0,8,4,12,2,10,6,14,1,9,5,13,3,11,7,15};

__device__ __forceinline__ float2 cmul(float2 a, float2 b)
{ return make_float2(a.x*b.x - a.y*b.y, a.x*b.y + a.y*b.x); }
__device__ __forceinline__ float2 cmulc(float2 a, float2 b)   // a * conj(b)
{ return make_float2(a.x*b.x + a.y*b.y, a.y*b.x - a.x*b.y); }

// W256^idx with only 128 table entries (sign fold)
__device__ __forceinline__ float2 twget(const float2* stw, int idx)
{
    idx &= 255;
    float2 w = stw[idx & 127];
    if (idx & 128) w = make_float2(-w.x, -w.y);
    return w;
}

// ---------------- prep (bit-identical to passing version) -------------------
__global__ void prep_kernel(const float* __restrict__ rows,
                            const float* __restrict__ shifts,
                            const float* __restrict__ latent,
                            const float* __restrict__ W0, const float* __restrict__ b0,
                            const float* __restrict__ W1, const float* __restrict__ b1,
                            const float* __restrict__ W2, const float* __restrict__ b2,
                            const float* __restrict__ W3, const float* __restrict__ b3)
{
    int t = threadIdx.x;
    if (t < 128) {
        float ang = -6.283185307179586f * (float)t / 256.0f;
        float s, c;
        sincosf(ang, &s, &c);
        g_tw[t] = make_float2(c, s);
    }
    if (t < Bb) {
        int b = t;
        float rot = rows[b*3+0], tilt = rows[b*3+1], psi = rows[b*3+2];
        float ca = cosf(rot),  sa = sinf(rot);
        float cb = cosf(tilt), sb = sinf(tilt);
        float cg = cosf(psi),  sg = sinf(psi);
        float cgcb = __fmul_rn(cg, cb);
        g_R[b*6+0] = __fsub_rn(__fmul_rn(cgcb, ca), __fmul_rn(sg, sa));
        g_R[b*6+1] = __fadd_rn(__fmul_rn(cgcb, sa), __fmul_rn(sg, ca));
        g_R[b*6+2] = __fmul_rn(-cg, sb);
        float msgcb = __fmul_rn(-sg, cb);
        g_R[b*6+3] = __fsub_rn(__fmul_rn(msgcb, ca), __fmul_rn(cg, sa));
        g_R[b*6+4] = __fadd_rn(__fmul_rn(msgcb, sa), __fmul_rn(cg, ca));
        g_R[b*6+5] = __fmul_rn(sg, sb);
        g_sh[b*2+0] = shifts[b*2+0];
        g_sh[b*2+1] = shifts[b*2+1];

        float h[LAT], l[LAT], tv[LAT];
        for (int i = 0; i < LAT; i++) l[i] = latent[b*LAT+i];
        for (int j = 0; j < LAT; j++) {
            float acc = 0.0f;
            for (int i = 0; i < LAT; i++) acc = __fmaf_rn(l[i], W0[i*LAT+j], acc);
            acc = __fadd_rn(acc, b0[j]);
            h[j] = sinf(30.0f * acc);
        }
        const float* Ws[3] = {W1, W2, W3};
        const float* bs[3] = {b1, b2, b3};
        for (int L = 0; L < 3; L++) {
            for (int j = 0; j < LAT; j++) {
                float acc = 0.0f;
                for (int i = 0; i < LAT; i++) acc = __fmaf_rn(h[i], Ws[L][i*LAT+j], acc);
                acc = __fadd_rn(acc, bs[L][j]);
                tv[j] = sinf(acc);
            }
            for (int j = 0; j < LAT; j++) h[j] = __fadd_rn(h[j], tv[j]);
        }
        for (int j = 0; j < LAT; j++) g_h[b*LAT+j] = h[j];
    }
}

// ---------------- zero image (vectorized) ------------------------------------
__global__ void zero_kernel()
{
    int i = blockIdx.x * blockDim.x + threadIdx.x;
    reinterpret_cast<float4*>(g_img)[i] = make_float4(0.f, 0.f, 0.f, 0.f);
}

// ---------------- scatter (bit-identical to passing version) ----------------
__global__ void scatter_kernel(const float* __restrict__ coords,
                               const float* __restrict__ values,
                               const float* __restrict__ Wd,
                               const float* __restrict__ bd)
{
    __shared__ float sR[Bb*6], sSh[Bb*2], sH[Bb*LAT];
    int t = threadIdx.x;
    if (t < Bb*6)   sR[t]  = g_R[t];
    if (t < Bb*2)   sSh[t] = g_sh[t];
    if (t < Bb*LAT) sH[t]  = g_h[t];
    __syncthreads();

    int n = blockIdx.x * blockDim.x + t;
    if (n >= NPTS) return;

    float c0 = coords[3*n+0];
    float c1 = coords[3*n+1];
    float c2 = coords[3*n+2];
    float val = values[n];
    float bdn = bd[n];

    float wd[LAT];
#pragma unroll
    for (int l = 0; l < LAT; l++) wd[l] = Wd[l*NPTS + n];

#pragma unroll
    for (int b = 0; b < Bb; b++) {
        float x = __fmul_rn(sR[b*6+0], c0);
        x = __fmaf_rn(sR[b*6+1], c1, x);
        x = __fmaf_rn(sR[b*6+2], c2, x);
        float y = __fmul_rn(sR[b*6+3], c0);
        y = __fmaf_rn(sR[b*6+4], c1, y);
        y = __fmaf_rn(sR[b*6+5], c2, y);
        x = __fadd_rn(__fadd_rn(x, sSh[b*2+0]), 128.0f);
        y = __fadd_rn(__fadd_rn(y, sSh[b*2+1]), 128.0f);
        float pxf = fminf(fmaxf(rintf(x), 0.0f), 255.0f);
        float pyf = fminf(fmaxf(rintf(y), 0.0f), 255.0f);
        int px = (int)pxf;
        int py = (int)pyf;

        float d = 0.0f;
#pragma unroll
        for (int l = 0; l < LAT; l++) d = __fmaf_rn(sH[b*LAT+l], wd[l], d);
        float contrib = __fadd_rn(val, __fadd_rn(d, bdn));

        int idx = (b << 16) | (py << 8) | px;
        atomicAdd(&g_img[idx], contrib);
    }
}

// ---------------- register-resident FFT16 (DIF, bitrev output) --------------
__device__ __forceinline__ void fft16_dif(float2* r, const float2* stw, bool conj_tw)
{
#pragma unroll
    for (int st = 0; st < 4; st++) {
        int half = 8 >> st;
#pragma unroll
        for (int base = 0; base < 16; base += 16 >> st) {
#pragma unroll
            for (int k = 0; k < 8; k++) {
                if (k < half) {
                    int i0 = base + k, i1 = i0 + half;
                    float2 u = r[i0], v = r[i1];
                    r[i0] = make_float2(u.x + v.x, u.y + v.y);
                    float2 d = make_float2(u.x - v.x, u.y - v.y);
                    float2 tw = stw[k << (4 + st)];      // W16^(k*2^st)
                    r[i1] = conj_tw ? cmulc(d, tw) : cmul(d, tw);
                }
            }
        }
    }
}

// DIT with conjugate twiddles: bit-reversed input -> natural output (inverse).
__device__ __forceinline__ void fft16_dit_conj(float2* r, const float2* stw)
{
#pragma unroll
    for (int st = 0; st < 4; st++) {
        int half = 1 << st;
#pragma unroll
        for (int base = 0; base < 16; base += 2 << st) {
#pragma unroll
            for (int k = 0; k < 8; k++) {
                if (k < half) {
                    int i0 = base + k, i1 = i0 + half;
                    float2 tw = stw[k << (7 - st)];
                    float2 u = r[i0];
                    float2 t = cmulc(r[i1], tw);
                    r[i0] = make_float2(u.x + t.x, u.y + t.y);
                    r[i1] = make_float2(u.x - t.x, u.y - t.y);
                }
            }
        }
    }
}

// ---------------- fused blur + forward row FFT, 16 rows/block ---------------
// Blur MAC order bit-identical to passing version. FFT256 via 16x16 four-step
// in registers (2x FFT16 + one smem transpose per row-pair).
#define GW0 0.39905027f
#define GW1 0.24203622f
#define GW2 0.05400558f
#define GW3 0.00443305f

__global__ void fwd_rows_blur2()
{
    __shared__ __align__(16) char smb[22528 + 16896];
    float*  raw   = (float*)smb;                    // 22 x 256 floats
    float*  ybl   = (float*)(smb + 22528);          // 16 x 264 floats
    float2* stage = (float2*)smb;                   // alias raw: 8 x 260 float2
    float2* zbuf  = (float2*)(smb + 22528);         // alias ybl: 8 x 260 float2
    __shared__ float2 stw[128];
    const float w[7] = {GW3, GW2, GW1, GW0, GW1, GW2, GW3};

    int tid = threadIdx.x;               // 128 threads
    int bid = blockIdx.x;                // Bb*16
    int b  = bid >> 4;
    int y0 = (bid & 15) << 4;
    int bbase = b << 16;

    stw[tid] = g_tw[tid];
    if (tid < 96) {                      // zero ybl col borders
        int r = tid / 6, p = tid - r * 6;
        int col = (p < 3) ? p : (256 + p);
        ybl[r * 264 + col] = 0.0f;
    }
    // load 22 halo rows (coalesced, zero outside)
    for (int i = tid; i < 22 * 256; i += 128) {
        int r = i >> 8, c = i & 255;
        int gy = y0 + r - 3;
        raw[i] = (gy >= 0 && gy < XS) ? g_img[bbase | (gy << 8) | c] : 0.0f;
    }
    __syncthreads();

    // y-pass: 16 rows x 256 cols
    for (int i = tid; i < 16 * 256; i += 128) {
        int r = i >> 8, c = i & 255;
        float acc = 0.0f;
#pragma unroll
        for (int d = 0; d < 7; d++)
            acc += w[d] * raw[((r + d) << 8) | c];
        ybl[r * 264 + 3 + c] = acc;
    }
    __syncthreads();

    // x-pass + pack row pairs into complex rows (stage aliases raw - done with it)
    for (int i = tid; i < 8 * 256; i += 128) {
        int g = i >> 8, c = i & 255;
        float a0 = 0.0f, a1 = 0.0f;
#pragma unroll
        for (int d = 0; d < 7; d++) {
            a0 += w[d] * ybl[(2 * g)     * 264 + c + d];
            a1 += w[d] * ybl[(2 * g + 1) * 264 + c + d];
        }
        stage[g * 260 + c] = make_float2(a0, a1);
    }
    __syncthreads();

    // four-step FFT256: thread (g, t): g = pair, t = n2 role
    int g = tid >> 4, t = tid & 15;
    float2 r[16];
#pragma unroll
    for (int n1 = 0; n1 < 16; n1++)
        r[n1] = stage[g * 260 + (n1 << 4) + t];
    __syncthreads();                     // all reads done before stage overwrite

    fft16_dif(r, stw, false);            // reg i: A[k1 = BR4[i]]
#pragma unroll
    for (int i = 0; i < 16; i++) {       // * W256^(t*k1), transpose write
        int k1 = BR4[i];
        stage[g * 260 + (k1 << 4) + t] = cmul(r[i], twget(stw, t * k1));
    }
    __syncthreads();

    float2 c[16];
#pragma unroll
    for (int n2 = 0; n2 < 16; n2++)      // thread role: k1 = t
        c[n2] = stage[g * 260 + (t << 4) + n2];
    fft16_dif(c, stw, false);            // reg i: Z[k = t + 16*BR4[i]]

#pragma unroll
    for (int i = 0; i < 16; i++)
        zbuf[g * 260 + (BR4[i] << 4) + t] = c[i];
    __syncthreads();

    // Hermitian unpack of packed 2-real-row spectrum; coalesced stores
    {
        int x = tid;                     // 0..127
#pragma unroll
        for (int gg = 0; gg < 8; gg++) {
            float2 Z  = zbuf[gg * 260 + x];
            float2 Zm = zbuf[gg * 260 + ((256 - x) & 255)];
            float2 F0 = make_float2(0.5f * (Z.x + Zm.x), 0.5f * (Z.y - Zm.y));
            float2 F1 = make_float2(0.5f * (Z.y + Zm.y), 0.5f * (Zm.x - Z.x));
            int r0 = (b * 256 + y0 + 2 * gg) * SSTR;
            g_S[r0 + x]        = F0;
            g_S[r0 + SSTR + x] = F1;
        }
        if (tid < 8) {                   // x = 128 (Nyquist)
            float2 Zn = zbuf[tid * 260 + 128];
            int r0 = (b * 256 + y0 + 2 * tid) * SSTR;
            g_S[r0 + 128]        = make_float2(Zn.x, 0.0f);
            g_S[r0 + SSTR + 128] = make_float2(Zn.y, 0.0f);
        }
    }
}

// ---------------- column pipeline: four-step 16x16, 16 x-cols per block ------
__global__ void fft_cols_ctf_k(const float* __restrict__ ctf)
{
    __shared__ float2 sm[256 * 17];
    __shared__ float2 stw[128];
    int t  = threadIdx.x;                 // 256
    int xi = t & 15, tb = t >> 4;
    int bid = blockIdx.x;                 // b*9 + tile
    int b = bid / 9, tile = bid - b * 9;
    int x = (tile << 4) + xi;
    bool xok = (x <= 128);
    if (t < 128) stw[t] = g_tw[t];
    __syncthreads();

    float2 r[16];
#pragma unroll
    for (int n1 = 0; n1 < 16; n1++)
        r[n1] = xok ? g_S[(b * 256 + (n1 << 4) + tb) * SSTR + x]
                    : make_float2(0.f, 0.f);
    fft16_dif(r, stw, false);

#pragma unroll
    for (int i = 0; i < 16; i++) {
        int k1 = BR4[i];
        int idx = (tb * k1) & 255;
        float2 tw = stw[idx & 127];
        if (idx & 128) tw = make_float2(-tw.x, -tw.y);
        sm[(k1 * 16 + tb) * 17 + xi] = cmul(r[i], tw);
    }
    __syncthreads();

    float2 c[16];
#pragma unroll
    for (int n2 = 0; n2 < 16; n2++)
        c[n2] = sm[(tb * 16 + n2) * 17 + xi];
    fft16_dif(c, stw, false);

#pragma unroll
    for (int i = 0; i < 16; i++) {
        int y = tb + (BR4[i] << 4);
        float cc = xok ? ctf[(b * 256 + y) * NXH + x] : 0.0f;
        c[i].x *= cc; c[i].y *= cc;
    }

    fft16_dit_conj(c, stw);
#pragma unroll
    for (int n2 = 0; n2 < 16; n2++) {
        int idx = (tb * n2) & 255;
        float2 tw = stw[idx & 127];
        if (idx & 128) tw = make_float2(-tw.x, -tw.y);
        c[n2] = cmulc(c[n2], tw);
    }
    __syncthreads();
#pragma unroll
    for (int n2 = 0; n2 < 16; n2++)
        sm[(n2 * 16 + tb) * 17 + xi] = c[n2];
    __syncthreads();

    float2 e[16];
#pragma unroll
    for (int k1 = 0; k1 < 16; k1++)
        e[k1] = sm[(tb * 16 + k1) * 17 + xi];
    fft16_dif(e, stw, true);

#pragma unroll
    for (int i = 0; i < 16; i++) {
        int y = (BR4[i] << 4) + tb;
        if (xok) g_S[(b * 256 + y) * SSTR + x] = e[i];
    }
}

// ---------------- inverse row FFT: four-step, 16 rows/block -----------------
// c2r semantics: imag of bins x=0,128 dropped at load.
__global__ void inv_rows2(float* __restrict__ out)
{
    __shared__ __align__(16) char smb[16640];
    float2* gr = (float2*)smb;            // 16 rows x 130  (16,640 B)
    float2* st = (float2*)smb;            // alias: 8 x 260
    __shared__ float2 stw[128];

    int tid = threadIdx.x;                // 128 threads
    int bid = blockIdx.x;                 // Bb*16
    int b  = bid >> 4;
    int y0 = (bid & 15) << 4;

    stw[tid] = g_tw[tid];
    // load rows y0..y0+15, cols 0..127 (coalesced)
#pragma unroll
    for (int r = 0; r < 16; r++)
        gr[r * 130 + tid] = g_S[(b * 256 + y0 + r) * SSTR + tid];
    __syncthreads();
    if (tid < 16) {                       // col 128 + imag-drop fixups
        gr[tid * 130 + 128] = make_float2(g_S[(b * 256 + y0 + tid) * SSTR + 128].x, 0.0f);
        gr[tid * 130 + 0].y = 0.0f;
    }
    __syncthreads();

    // build Z registers for this pair: Z[n], n = 16*i + t
    int g = tid >> 4, t = tid & 15;
    const float2* G0 = gr + (2 * g) * 130;
    const float2* G1 = gr + (2 * g + 1) * 130;
    float2 z[16];
#pragma unroll
    for (int i = 0; i < 16; i++) {
        int n = (i << 4) + t;
        float2 zz;
        if (n <= 128) {
            float2 a = G0[n], cc = G1[n];
            zz = make_float2(a.x - cc.y, a.y + cc.x);
        } else {
            int m = 256 - n;
            float2 a = G0[m], cc = G1[m];
            zz = make_float2(a.x + cc.y, cc.x - a.y);
        }
        z[i] = zz;
    }
    __syncthreads();                      // all gr reads done before st overwrite

    // inverse four-step: FFT16conj over i -> *W^-(t*k1) -> transpose -> FFT16conj
    fft16_dif(z, stw, true);              // reg i: B[k1 = BR4[i]]
#pragma unroll
    for (int i = 0; i < 16; i++) {
        int k1 = BR4[i];
        st[g * 260 + (k1 << 4) + t] = cmulc(z[i], twget(stw, t * k1));
    }
    __syncthreads();

    float2 c[16];
#pragma unroll
    for (int n2 = 0; n2 < 16; n2++)       // thread role: m = t
        c[n2] = st[g * 260 + (t << 4) + n2];
    __syncthreads();                      // reads done before xbuf overwrite
    fft16_dif(c, stw, true);              // reg i: x[n = t + 16*BR4[i]]

#pragma unroll
    for (int i = 0; i < 16; i++)
        st[g * 260 + (BR4[i] << 4) + t] = c[i];
    __syncthreads();

    // write out: row 2g from .x, row 2g+1 from .y, scaled
    const float norm = 1.0f / 65536.0f;
    for (int i = tid; i < 8 * 256; i += 128) {
        int gg = i >> 8, cc = i & 255;
        float2 v = st[gg * 260 + cc];
        int off0 = (b << 16) | ((y0 + 2 * gg) << 8);
        out[off0 + cc]       = v.x * norm;
        out[off0 + 256 + cc] = v.y * norm;
    }
}

// ---------------- launch -----------------------------------------------------
extern "C" void kernel_launch(void* const* d_in, const int* in_sizes, int n_in,
                              void* d_out, int out_size)
{
    const float* rows   = (const float*)d_in[0];
    const float* shifts = (const float*)d_in[1];
    const float* latent = (const float*)d_in[2];
    const float* coords = (const float*)d_in[3];
    const float* values = (const float*)d_in[4];
    const float* W0     = (const float*)d_in[5];
    const float* b0     = (const float*)d_in[6];
    const float* W1     = (const float*)d_in[7];
    const float* b1     = (const float*)d_in[8];
    const float* W2     = (const float*)d_in[9];
    const float* b2     = (const float*)d_in[10];
    const float* W3     = (const float*)d_in[11];
    const float* b3     = (const float*)d_in[12];
    const float* Wd     = (const float*)d_in[13];
    const float* bd     = (const float*)d_in[14];
    const float* ctf    = (const float*)d_in[15];
    float* out = (float*)d_out;

    prep_kernel<<<1, 128>>>(rows, shifts, latent, W0, b0, W1, b1, W2, b2, W3, b3);
    zero_kernel<<<IMG_ELEMS / 4 / 256, 256>>>();
    scatter_kernel<<<(NPTS + 255) / 256, 256>>>(coords, values, Wd, bd);
    fwd_rows_blur2<<<Bb * 16, 128>>>();
    fft_cols_ctf_k<<<Bb * 9, 256>>>(ctf);
    inv_rows2<<<Bb * 16, 128>>>(out);
}

// round 9
// speedup vs baseline: 1.9047x; 1.0912x over previous
#include <cuda_runtime.h>
#include <cuda_bf16.h>
#include <cstdint>

#define Bb   16
#define LAT  8
#define NPTS 500000
#define XS   256
#define IMG_ELEMS (Bb * XS * XS)   // 1,048,576
#define NXH  129                   // Hermitian half-spectrum width
#define SSTR 132                   // g_S row stride (float2)

// ---------------- device scratch (static, no runtime allocation) ------------
__device__ float  g_img[IMG_ELEMS];            // 4 MB (scatter accumulator)
__device__ float2 g_S[Bb * XS * SSTR];         // 4.3 MB half spectrum [b][y][x]
__device__ float  g_R[Bb * 6];
__device__ float  g_sh[Bb * 2];
__device__ float  g_h[Bb * LAT];
__device__ float2 g_tw[128];                   // exp(-2*pi*i*k/256)

#define REV8(i) ((int)(__brev((unsigned)(i)) >> 24))
__device__ __constant__ int BR4[16] = {0,8,4,12,2,10,6,14,1,9,5,13,3,11,7,15};

__device__ __forceinline__ float2 cmul(float2 a, float2 b)
{ return make_float2(a.x*b.x - a.y*b.y, a.x*b.y + a.y*b.x); }
__device__ __forceinline__ float2 cmulc(float2 a, float2 b)   // a * conj(b)
{ return make_float2(a.x*b.x + a.y*b.y, a.y*b.x - a.x*b.y); }

__device__ __forceinline__ float2 twget(const float2* stw, int idx)
{
    idx &= 255;
    float2 w = stw[idx & 127];
    if (idx & 128) w = make_float2(-w.x, -w.y);
    return w;
}

// ---------------- prep (bit-identical to passing version) -------------------
__global__ void prep_kernel(const float* __restrict__ rows,
                            const float* __restrict__ shifts,
                            const float* __restrict__ latent,
                            const float* __restrict__ W0, const float* __restrict__ b0,
                            const float* __restrict__ W1, const float* __restrict__ b1,
                            const float* __restrict__ W2, const float* __restrict__ b2,
                            const float* __restrict__ W3, const float* __restrict__ b3)
{
    int t = threadIdx.x;
    if (t < 128) {
        float ang = -6.283185307179586f * (float)t / 256.0f;
        float s, c;
        sincosf(ang, &s, &c);
        g_tw[t] = make_float2(c, s);
    }
    if (t < Bb) {
        int b = t;
        float rot = rows[b*3+0], tilt = rows[b*3+1], psi = rows[b*3+2];
        float ca = cosf(rot),  sa = sinf(rot);
        float cb = cosf(tilt), sb = sinf(tilt);
        float cg = cosf(psi),  sg = sinf(psi);
        float cgcb = __fmul_rn(cg, cb);
        g_R[b*6+0] = __fsub_rn(__fmul_rn(cgcb, ca), __fmul_rn(sg, sa));
        g_R[b*6+1] = __fadd_rn(__fmul_rn(cgcb, sa), __fmul_rn(sg, ca));
        g_R[b*6+2] = __fmul_rn(-cg, sb);
        float msgcb = __fmul_rn(-sg, cb);
        g_R[b*6+3] = __fsub_rn(__fmul_rn(msgcb, ca), __fmul_rn(cg, sa));
        g_R[b*6+4] = __fadd_rn(__fmul_rn(msgcb, sa), __fmul_rn(cg, ca));
        g_R[b*6+5] = __fmul_rn(sg, sb);
        g_sh[b*2+0] = shifts[b*2+0];
        g_sh[b*2+1] = shifts[b*2+1];

        float h[LAT], l[LAT], tv[LAT];
        for (int i = 0; i < LAT; i++) l[i] = latent[b*LAT+i];
        for (int j = 0; j < LAT; j++) {
            float acc = 0.0f;
            for (int i = 0; i < LAT; i++) acc = __fmaf_rn(l[i], W0[i*LAT+j], acc);
            acc = __fadd_rn(acc, b0[j]);
            h[j] = sinf(30.0f * acc);
        }
        const float* Ws[3] = {W1, W2, W3};
        const float* bs[3] = {b1, b2, b3};
        for (int L = 0; L < 3; L++) {
            for (int j = 0; j < LAT; j++) {
                float acc = 0.0f;
                for (int i = 0; i < LAT; i++) acc = __fmaf_rn(h[i], Ws[L][i*LAT+j], acc);
                acc = __fadd_rn(acc, bs[L][j]);
                tv[j] = sinf(acc);
            }
            for (int j = 0; j < LAT; j++) h[j] = __fadd_rn(h[j], tv[j]);
        }
        for (int j = 0; j < LAT; j++) g_h[b*LAT+j] = h[j];
    }
}

// ---------------- zero image (vectorized) ------------------------------------
__global__ void zero_kernel()
{
    int i = blockIdx.x * blockDim.x + threadIdx.x;
    reinterpret_cast<float4*>(g_img)[i] = make_float4(0.f, 0.f, 0.f, 0.f);
}

// ---------------- scatter (bit-identical to passing version) ----------------
__global__ void scatter_kernel(const float* __restrict__ coords,
                               const float* __restrict__ values,
                               const float* __restrict__ Wd,
                               const float* __restrict__ bd)
{
    __shared__ float sR[Bb*6], sSh[Bb*2], sH[Bb*LAT];
    int t = threadIdx.x;
    if (t < Bb*6)   sR[t]  = g_R[t];
    if (t < Bb*2)   sSh[t] = g_sh[t];
    if (t < Bb*LAT) sH[t]  = g_h[t];
    __syncthreads();

    int n = blockIdx.x * blockDim.x + t;
    if (n >= NPTS) return;

    float c0 = coords[3*n+0];
    float c1 = coords[3*n+1];
    float c2 = coords[3*n+2];
    float val = values[n];
    float bdn = bd[n];

    float wd[LAT];
#pragma unroll
    for (int l = 0; l < LAT; l++) wd[l] = Wd[l*NPTS + n];

#pragma unroll
    for (int b = 0; b < Bb; b++) {
        float x = __fmul_rn(sR[b*6+0], c0);
        x = __fmaf_rn(sR[b*6+1], c1, x);
        x = __fmaf_rn(sR[b*6+2], c2, x);
        float y = __fmul_rn(sR[b*6+3], c0);
        y = __fmaf_rn(sR[b*6+4], c1, y);
        y = __fmaf_rn(sR[b*6+5], c2, y);
        x = __fadd_rn(__fadd_rn(x, sSh[b*2+0]), 128.0f);
        y = __fadd_rn(__fadd_rn(y, sSh[b*2+1]), 128.0f);
        float pxf = fminf(fmaxf(rintf(x), 0.0f), 255.0f);
        float pyf = fminf(fmaxf(rintf(y), 0.0f), 255.0f);
        int px = (int)pxf;
        int py = (int)pyf;

        float d = 0.0f;
#pragma unroll
        for (int l = 0; l < LAT; l++) d = __fmaf_rn(sH[b*LAT+l], wd[l], d);
        float contrib = __fadd_rn(val, __fadd_rn(d, bdn));

        int idx = (b << 16) | (py << 8) | px;
        atomicAdd(&g_img[idx], contrib);
    }
}

// ---------------- register-resident FFT16 (DIF, bitrev output) --------------
__device__ __forceinline__ void fft16_dif(float2* r, const float2* stw, bool conj_tw)
{
#pragma unroll
    for (int st = 0; st < 4; st++) {
        int half = 8 >> st;
#pragma unroll
        for (int base = 0; base < 16; base += 16 >> st) {
#pragma unroll
            for (int k = 0; k < 8; k++) {
                if (k < half) {
                    int i0 = base + k, i1 = i0 + half;
                    float2 u = r[i0], v = r[i1];
                    r[i0] = make_float2(u.x + v.x, u.y + v.y);
                    float2 d = make_float2(u.x - v.x, u.y - v.y);
                    float2 tw = stw[k << (4 + st)];      // W16^(k*2^st)
                    r[i1] = conj_tw ? cmulc(d, tw) : cmul(d, tw);
                }
            }
        }
    }
}

// DIT with conjugate twiddles: bit-reversed input -> natural output (inverse).
__device__ __forceinline__ void fft16_dit_conj(float2* r, const float2* stw)
{
#pragma unroll
    for (int st = 0; st < 4; st++) {
        int half = 1 << st;
#pragma unroll
        for (int base = 0; base < 16; base += 2 << st) {
#pragma unroll
            for (int k = 0; k < 8; k++) {
                if (k < half) {
                    int i0 = base + k, i1 = i0 + half;
                    float2 tw = stw[k << (7 - st)];
                    float2 u = r[i0];
                    float2 t = cmulc(r[i1], tw);
                    r[i0] = make_float2(u.x + t.x, u.y + t.y);
                    r[i1] = make_float2(u.x - t.x, u.y - t.y);
                }
            }
        }
    }
}

// ---------------- fused blur + forward row FFT, 8 rows/block ----------------
// 256 threads, grid Bb*32 = 512. Blur MAC order bit-identical. float4 halo.
#define GW0 0.39905027f
#define GW1 0.24203622f
#define GW2 0.05400558f
#define GW3 0.00443305f

__global__ void fwd_rows_blur3()
{
    __shared__ __align__(16) char smb[14336 + 8448];
    float*  raw   = (float*)smb;                    // 14 x 256 floats
    float*  ybl   = (float*)(smb + 14336);          // 8 x 264 floats
    float2* stage = (float2*)smb;                   // alias raw: 4 x 260 float2
    float2* zbuf  = (float2*)(smb + 14336);         // alias ybl: 4 x 260 float2
    __shared__ float2 stw[128];
    const float w[7] = {GW3, GW2, GW1, GW0, GW1, GW2, GW3};

    int tid = threadIdx.x;               // 256 threads
    int bid = blockIdx.x;                // Bb*32
    int b  = bid >> 5;
    int y0 = (bid & 31) << 3;

    if (tid < 128) stw[tid] = g_tw[tid];
    if (tid < 48) {                      // zero ybl col borders (8 rows x 6)
        int r = tid / 6, p = tid - r * 6;
        int col = (p < 3) ? p : (256 + p);
        ybl[r * 264 + col] = 0.0f;
    }
    // load 14 halo rows as float4 (coalesced, zero outside)
    const float4* img4 = reinterpret_cast<const float4*>(g_img);
    float4* raw4 = reinterpret_cast<float4*>(raw);
    for (int i = tid; i < 14 * 64; i += 256) {
        int r = i >> 6, c4 = i & 63;
        int gy = y0 + r - 3;
        float4 v = make_float4(0.f, 0.f, 0.f, 0.f);
        if (gy >= 0 && gy < XS)
            v = img4[(b << 14) | (gy << 6) | c4];
        raw4[i] = v;
    }
    __syncthreads();

    // y-pass: 8 rows x 256 cols
    for (int i = tid; i < 8 * 256; i += 256) {
        int r = i >> 8, c = i & 255;
        float acc = 0.0f;
#pragma unroll
        for (int d = 0; d < 7; d++)
            acc += w[d] * raw[((r + d) << 8) | c];
        ybl[r * 264 + 3 + c] = acc;
    }
    __syncthreads();

    // x-pass + pack row pairs (stage aliases raw; raw reads finished)
    for (int i = tid; i < 4 * 256; i += 256) {
        int g = i >> 8, c = i & 255;
        float a0 = 0.0f, a1 = 0.0f;
#pragma unroll
        for (int d = 0; d < 7; d++) {
            a0 += w[d] * ybl[(2 * g)     * 264 + c + d];
            a1 += w[d] * ybl[(2 * g + 1) * 264 + c + d];
        }
        stage[g * 260 + c] = make_float2(a0, a1);
    }
    __syncthreads();

    // four-step FFT256 on 4 pairs: roles tid<64 (g = tid>>4, t = tid&15)
    bool act = (tid < 64);
    int g = tid >> 4, t = tid & 15;
    float2 r[16];
    if (act) {
#pragma unroll
        for (int n1 = 0; n1 < 16; n1++)
            r[n1] = stage[g * 260 + (n1 << 4) + t];
        fft16_dif(r, stw, false);        // reg i: A[k1 = BR4[i]]
        // thread owns column t exclusively -> safe in-place transpose write
#pragma unroll
        for (int i = 0; i < 16; i++) {
            int k1 = BR4[i];
            stage[g * 260 + (k1 << 4) + t] = cmul(r[i], twget(stw, t * k1));
        }
    }
    __syncthreads();

    float2 c[16];
    if (act) {
#pragma unroll
        for (int n2 = 0; n2 < 16; n2++)  // thread role: k1 = t
            c[n2] = stage[g * 260 + (t << 4) + n2];
        fft16_dif(c, stw, false);        // reg i: Z[k = t + 16*BR4[i]]
#pragma unroll
        for (int i = 0; i < 16; i++)
            zbuf[g * 260 + (BR4[i] << 4) + t] = c[i];
    }
    __syncthreads();

    // Hermitian unpack; coalesced stores (4 pairs x 128 x-values)
    for (int i = tid; i < 4 * 128; i += 256) {
        int gg = i >> 7, x = i & 127;
        float2 Z  = zbuf[gg * 260 + x];
        float2 Zm = zbuf[gg * 260 + ((256 - x) & 255)];
        float2 F0 = make_float2(0.5f * (Z.x + Zm.x), 0.5f * (Z.y - Zm.y));
        float2 F1 = make_float2(0.5f * (Z.y + Zm.y), 0.5f * (Zm.x - Z.x));
        int r0 = (b * 256 + y0 + 2 * gg) * SSTR;
        g_S[r0 + x]        = F0;
        g_S[r0 + SSTR + x] = F1;
    }
    if (tid < 4) {                       // x = 128 (Nyquist)
        float2 Zn = zbuf[tid * 260 + 128];
        int r0 = (b * 256 + y0 + 2 * tid) * SSTR;
        g_S[r0 + 128]        = make_float2(Zn.x, 0.0f);
        g_S[r0 + SSTR + 128] = make_float2(Zn.y, 0.0f);
    }
}

// ---------------- column pipeline: four-step 16x16, 16 x-cols per block ------
__global__ void fft_cols_ctf_k(const float* __restrict__ ctf)
{
    __shared__ float2 sm[256 * 17];
    __shared__ float2 stw[128];
    int t  = threadIdx.x;                 // 256
    int xi = t & 15, tb = t >> 4;
    int bid = blockIdx.x;                 // b*9 + tile
    int b = bid / 9, tile = bid - b * 9;
    int x = (tile << 4) + xi;
    bool xok = (x <= 128);
    if (t < 128) stw[t] = g_tw[t];
    __syncthreads();

    float2 r[16];
#pragma unroll
    for (int n1 = 0; n1 < 16; n1++)
        r[n1] = xok ? g_S[(b * 256 + (n1 << 4) + tb) * SSTR + x]
                    : make_float2(0.f, 0.f);
    fft16_dif(r, stw, false);

#pragma unroll
    for (int i = 0; i < 16; i++) {
        int k1 = BR4[i];
        sm[(k1 * 16 + tb) * 17 + xi] = cmul(r[i], twget(stw, tb * k1));
    }
    __syncthreads();

    float2 c[16];
#pragma unroll
    for (int n2 = 0; n2 < 16; n2++)
        c[n2] = sm[(tb * 16 + n2) * 17 + xi];
    fft16_dif(c, stw, false);

#pragma unroll
    for (int i = 0; i < 16; i++) {
        int y = tb + (BR4[i] << 4);
        float cc = xok ? ctf[(b * 256 + y) * NXH + x] : 0.0f;
        c[i].x *= cc; c[i].y *= cc;
    }

    fft16_dit_conj(c, stw);
#pragma unroll
    for (int n2 = 0; n2 < 16; n2++)
        c[n2] = cmulc(c[n2], twget(stw, tb * n2));
    __syncthreads();
#pragma unroll
    for (int n2 = 0; n2 < 16; n2++)
        sm[(n2 * 16 + tb) * 17 + xi] = c[n2];
    __syncthreads();

    float2 e[16];
#pragma unroll
    for (int k1 = 0; k1 < 16; k1++)
        e[k1] = sm[(tb * 16 + k1) * 17 + xi];
    fft16_dif(e, stw, true);

#pragma unroll
    for (int i = 0; i < 16; i++) {
        int y = (BR4[i] << 4) + tb;
        if (xok) g_S[(b * 256 + y) * SSTR + x] = e[i];
    }
}

// ---------------- inverse row FFT: four-step, 8 rows/block ------------------
// 128 threads, grid Bb*32 = 512. c2r: imag of bins x=0,128 dropped at load.
__global__ void inv_rows3(float* __restrict__ out)
{
    __shared__ __align__(16) char smb[8320];
    float2* gr = (float2*)smb;            // 8 rows x 130
    float2* st = (float2*)smb;            // alias: 4 x 260
    __shared__ float2 stw[128];

    int tid = threadIdx.x;                // 128 threads
    int bid = blockIdx.x;                 // Bb*32
    int b  = bid >> 5;
    int y0 = (bid & 31) << 3;

    stw[tid] = g_tw[tid];
    // load rows y0..y0+7, cols 0..127 (coalesced)
#pragma unroll
    for (int r = 0; r < 8; r++)
        gr[r * 130 + tid] = g_S[(b * 256 + y0 + r) * SSTR + tid];
    __syncthreads();
    if (tid < 8) {                        // col 128 + imag-drop fixups
        gr[tid * 130 + 128] = make_float2(g_S[(b * 256 + y0 + tid) * SSTR + 128].x, 0.0f);
        gr[tid * 130 + 0].y = 0.0f;
    }
    __syncthreads();

    // build Z registers: roles tid<64 (g = tid>>4, t = tid&15)
    bool act = (tid < 64);
    int g = tid >> 4, t = tid & 15;
    float2 z[16];
    if (act) {
        const float2* G0 = gr + (2 * g) * 130;
        const float2* G1 = gr + (2 * g + 1) * 130;
#pragma unroll
        for (int i = 0; i < 16; i++) {
            int n = (i << 4) + t;
            float2 zz;
            if (n <= 128) {
                float2 a = G0[n], cc = G1[n];
                zz = make_float2(a.x - cc.y, a.y + cc.x);
            } else {
                int m = 256 - n;
                float2 a = G0[m], cc = G1[m];
                zz = make_float2(a.x + cc.y, cc.x - a.y);
            }
            z[i] = zz;
        }
    }
    __syncthreads();                      // all gr reads done before st overwrite

    if (act) {
        fft16_dif(z, stw, true);          // reg i: B[k1 = BR4[i]]
#pragma unroll
        for (int i = 0; i < 16; i++) {
            int k1 = BR4[i];
            st[g * 260 + (k1 << 4) + t] = cmulc(z[i], twget(stw, t * k1));
        }
    }
    __syncthreads();

    float2 c[16];
    if (act) {
#pragma unroll
        for (int n2 = 0; n2 < 16; n2++)   // thread role: m = t
            c[n2] = st[g * 260 + (t << 4) + n2];
        fft16_dif(c, stw, true);          // reg i: x[n = t + 16*BR4[i]]
#pragma unroll
        for (int i = 0; i < 16; i++)
            st[g * 260 + (BR4[i] << 4) + t] = c[i];
    }
    __syncthreads();

    // write out: row 2g from .x, row 2g+1 from .y, scaled
    const float norm = 1.0f / 65536.0f;
    for (int i = tid; i < 4 * 256; i += 128) {
        int gg = i >> 8, cc = i & 255;
        float2 v = st[gg * 260 + cc];
        int off0 = (b << 16) | ((y0 + 2 * gg) << 8);
        out[off0 + cc]       = v.x * norm;
        out[off0 + 256 + cc] = v.y * norm;
    }
}

// ---------------- launch -----------------------------------------------------
extern "C" void kernel_launch(void* const* d_in, const int* in_sizes, int n_in,
                              void* d_out, int out_size)
{
    const float* rows   = (const float*)d_in[0];
    const float* shifts = (const float*)d_in[1];
    const float* latent = (const float*)d_in[2];
    const float* coords = (const float*)d_in[3];
    const float* values = (const float*)d_in[4];
    const float* W0     = (const float*)d_in[5];
    const float* b0     = (const float*)d_in[6];
    const float* W1     = (const float*)d_in[7];
    const float* b1     = (const float*)d_in[8];
    const float* W2     = (const float*)d_in[9];
    const float* b2     = (const float*)d_in[10];
    const float* W3     = (const float*)d_in[11];
    const float* b3     = (const float*)d_in[12];
    const float* Wd     = (const float*)d_in[13];
    const float* bd     = (const float*)d_in[14];
    const float* ctf    = (const float*)d_in[15];
    float* out = (float*)d_out;

    prep_kernel<<<1, 128>>>(rows, shifts, latent, W0, b0, W1, b1, W2, b2, W3, b3);
    zero_kernel<<<IMG_ELEMS / 4 / 256, 256>>>();
    scatter_kernel<<<(NPTS + 255) / 256, 256>>>(coords, values, Wd, bd);
    fwd_rows_blur3<<<Bb * 32, 256>>>();
    fft_cols_ctf_k<<<Bb * 9, 256>>>(ctf);
    inv_rows3<<<Bb * 32, 128>>>(out);
}